// round 16
// baseline (speedup 1.0000x reference)
#include <cuda_runtime.h>
#include <math.h>

typedef unsigned long long u64;

// ---------------- scratch (device globals; no allocation allowed) ----------
__device__ __align__(16) float g_w2k[50 * 20 * 5 * 8];  // w2 [oc][c][kh][8] (pad 5->8)
__device__ __align__(16) float g_s2mm[128 * 50 * 4 * 8]; // s2 window [b][oc][prow][max4|min4]
__device__ float g_plog[128 * 8 * 10];       // partial logits [b][slice][10]

__device__ float g_bsum1[20 * 128], g_bsq1[20 * 128];
__device__ float g_bsum2[50 * 128], g_bsq2[50 * 128];

__device__ u64 g_barctr = 0;  // monotonic epoch barrier counter

// grid-wide barrier: monotonic counter, safe across graph replays
__device__ __forceinline__ void grid_barrier() {
    __syncthreads();
    if (threadIdx.x == 0) {
        __threadfence();
        u64 old = atomicAdd(&g_barctr, 1ULL);
        u64 target = (old / gridDim.x + 1ULL) * (u64)gridDim.x;
        while (*((volatile u64*)&g_barctr) < target) { }
        __threadfence();
    }
    __syncthreads();
}

#define CSTR 148   // padded channel stride (words): 5*CSTR % 32 == 4 -> conflict-free

// ---------------- shared memory layout ---------------------------------------
struct AB {
    float pmax[20 * CSTR];   // pooled-window max of conv1 [c][prow*12+pcol]
    float pmin[20 * CSTR];   // pooled-window min
    union {
        struct { float xs[784]; float ws[500]; float red_s[960]; float red_q[960]; } a;
        struct { float s1s[20]; float s1b[20]; float red_s[200]; float red_q[200]; } b;
    } u;
};
struct SC { float p_s[8][800]; float s2s[50]; float s2b[50]; float hs[64][8]; };
struct SD { float logits[10]; };
union SU { AB ab; SC c; SD d; };

// ---------------- mega kernel ----------------------------------------------
__global__ __launch_bounds__(1024, 1) void mega_k(
    const float* __restrict__ x,      const float* __restrict__ w1,
    const float* __restrict__ gamma1, const float* __restrict__ beta1,
    const float* __restrict__ w2,
    const float* __restrict__ gamma2, const float* __restrict__ beta2,
    const float* __restrict__ fc1_w,  const float* __restrict__ fc1_b,
    const float* __restrict__ fc2_w,  const float* __restrict__ fc2_b,
    float* __restrict__ out)
{
    __shared__ __align__(16) SU sm;

    const int blk  = blockIdx.x;        // 0..127
    const int tid  = threadIdx.x;
    const int wid  = tid / 32;
    const int lane = tid % 32;

    // ======================= STAGE A: adder1 (+ w2 repack) =================
    {
        const int b = blk;
        // w2 repack slice -> kh-major padded layout: 128 blocks x 196 >= 25000
        {
            const int i = b * 196 + tid;
            if (tid < 196 && i < 25000) {
                const int oc = i / 500;
                const int r  = i % 500;
                const int c  = r / 25;
                const int k  = r % 25;
                g_w2k[(((oc * 20 + c) * 5 + (k / 5)) * 8) + (k % 5)] = w2[i];
            }
        }
        for (int i = tid; i < 784; i += 1024) sm.ab.u.a.xs[i] = x[b * 784 + i];
        for (int i = tid; i < 500; i += 1024) sm.ab.u.a.ws[i] = w1[i];
        __syncthreads();

        if (tid < 960) {
            const int oc   = tid / 48;
            const int r    = tid % 48;
            const int half = r / 24;          // pw block: half*12 .. half*12+11
            const int ph   = r % 24;          // (ph, ph^1) pairs on adjacent lanes

            float acc[12];
#pragma unroll
            for (int p = 0; p < 12; p++) acc[p] = 0.f;

#pragma unroll
            for (int kh = 0; kh < 5; kh++) {
                const float4* xrow = (const float4*)(sm.ab.u.a.xs + (ph + kh) * 28 + half * 12);
                float xr[16];
                float4 v0 = xrow[0], v1 = xrow[1], v2 = xrow[2], v3 = xrow[3];
                xr[0]=v0.x; xr[1]=v0.y; xr[2]=v0.z; xr[3]=v0.w;
                xr[4]=v1.x; xr[5]=v1.y; xr[6]=v1.z; xr[7]=v1.w;
                xr[8]=v2.x; xr[9]=v2.y; xr[10]=v2.z; xr[11]=v2.w;
                xr[12]=v3.x; xr[13]=v3.y; xr[14]=v3.z; xr[15]=v3.w;
#pragma unroll
                for (int kw = 0; kw < 5; kw++) {
                    const float w = sm.ab.u.a.ws[oc * 25 + kh * 5 + kw];
#pragma unroll
                    for (int p = 0; p < 12; p++) {
                        float d = fmaf(w, -1.0f, xr[p + kw]);          // FFMA-imm rt1
                        acc[p]  = fmaf(fabsf(d), -1.0f, acc[p]);       // FFMA-imm rt1
                    }
                }
            }

            // BN partials on raw values
            float lsum = 0.f, lsq = 0.f;
#pragma unroll
            for (int p = 0; p < 12; p++) { lsum += acc[p]; lsq += acc[p] * acc[p]; }
            sm.ab.u.a.red_s[tid] = lsum;
            sm.ab.u.a.red_q[tid] = lsq;

            // column-pair max/min, then row-pair via shuffle with lane+1
            float cmx[6], cmn[6];
#pragma unroll
            for (int j = 0; j < 6; j++) {
                cmx[j] = fmaxf(acc[2*j], acc[2*j+1]);
                cmn[j] = fminf(acc[2*j], acc[2*j+1]);
            }
#pragma unroll
            for (int j = 0; j < 6; j++) {
                float omx = __shfl_down_sync(0xffffffffu, cmx[j], 1);
                float omn = __shfl_down_sync(0xffffffffu, cmn[j], 1);
                cmx[j] = fmaxf(cmx[j], omx);
                cmn[j] = fminf(cmn[j], omn);
            }
            if ((ph & 1) == 0) {
                const int prow = ph >> 1;
                const int base = oc * CSTR + prow * 12 + half * 6;
#pragma unroll
                for (int j = 0; j < 6; j++) {
                    sm.ab.pmax[base + j] = cmx[j];
                    sm.ab.pmin[base + j] = cmn[j];
                }
            }
        }
        __syncthreads();

        if (tid < 960 && (tid % 48) == 0) {   // 20 threads, deterministic
            const int oc = tid / 48;
            float s = 0.f, q = 0.f;
            for (int t = 0; t < 48; t++) { s += sm.ab.u.a.red_s[oc * 48 + t]; q += sm.ab.u.a.red_q[oc * 48 + t]; }
            g_bsum1[oc * 128 + b] = s;
            g_bsq1[oc * 128 + b]  = q;
        }
    }

    grid_barrier();

    // ======================= STAGE B: bn1+pool (in smem) + adder2 ==========
    // thread = (oc 0..49, sub = cquarter*4 + phpair): 2 output rows, 5 channels
    {
        const int b = blk;

        // bnparam1: warp per channel (redundant per block, deterministic)
        if (wid < 20) {
            float s = 0.f, q = 0.f;
#pragma unroll
            for (int i = 0; i < 4; i++) {
                const int bb = lane + 32 * i;
                s += g_bsum1[wid * 128 + bb];
                q += g_bsq1[wid * 128 + bb];
            }
#pragma unroll
            for (int d = 16; d; d >>= 1) {
                s += __shfl_xor_sync(0xffffffffu, s, d);
                q += __shfl_xor_sync(0xffffffffu, q, d);
            }
            if (lane == 0) {
                const float invN = 1.f / (128.f * 24.f * 24.f);
                float m = s * invN;
                float v = q * invN - m * m;
                float sc = gamma1[wid] * rsqrtf(v + 1e-5f);
                sm.ab.u.b.s1s[wid] = sc;
                sm.ab.u.b.s1b[wid] = beta1[wid] - m * sc;
            }
        }
        __syncthreads();

        // bn1 + pool, in place over pmax: pool = max(s*mx+be, s*mn+be)
        for (int i = tid; i < 20 * CSTR; i += 1024) {
            const int c   = i / CSTR;
            const int rem = i % CSTR;
            if (rem < 144) {
                const float s = sm.ab.u.b.s1s[c], be = sm.ab.u.b.s1b[c];
                float v = fmaxf(fmaf(s, sm.ab.pmax[i], be), fmaf(s, sm.ab.pmin[i], be));
                sm.ab.pmax[i] = v;
            }
        }
        __syncthreads();

        if (tid < 800) {
            const int oc     = tid / 16;
            const int sub    = tid % 16;
            const int q      = sub >> 2;        // c quarter: q*5 .. q*5+4
            const int phpair = sub & 3;         // rows ph0, ph0+1
            const int ph0    = phpair * 2;

            float acc0[8], acc1[8];
#pragma unroll
            for (int p = 0; p < 8; p++) { acc0[p] = 0.f; acc1[p] = 0.f; }

#pragma unroll
            for (int cc = 0; cc < 5; cc++) {
                const int c = q * 5 + cc;
                const float* xc = sm.ab.pmax + c * CSTR + ph0 * 12;
                const float4* wk = (const float4*)(g_w2k + ((oc * 20 + c) * 5) * 8);

                float wprev[5];
#pragma unroll
                for (int r = 0; r < 6; r++) {
                    float wcur[5];
                    if (r < 5) {
                        float4 wa = wk[r * 2];
                        float4 wb = wk[r * 2 + 1];
                        wcur[0] = wa.x; wcur[1] = wa.y; wcur[2] = wa.z;
                        wcur[3] = wa.w; wcur[4] = wb.x;
                    }
                    const float4* xrow = (const float4*)(xc + r * 12);
                    float4 v0 = xrow[0], v1 = xrow[1], v2 = xrow[2];
                    float xr[12];
                    xr[0]=v0.x; xr[1]=v0.y; xr[2]=v0.z; xr[3]=v0.w;
                    xr[4]=v1.x; xr[5]=v1.y; xr[6]=v1.z; xr[7]=v1.w;
                    xr[8]=v2.x; xr[9]=v2.y; xr[10]=v2.z; xr[11]=v2.w;

                    if (r < 5) {   // row0: kh = r
#pragma unroll
                        for (int kw = 0; kw < 5; kw++) {
                            const float w = wcur[kw];
#pragma unroll
                            for (int p = 0; p < 8; p++) {
                                float d = fmaf(w, -1.0f, xr[p + kw]);
                                acc0[p] = fmaf(fabsf(d), -1.0f, acc0[p]);
                            }
                        }
                    }
                    if (r >= 1) {  // row1: kh = r-1
#pragma unroll
                        for (int kw = 0; kw < 5; kw++) {
                            const float w = wprev[kw];
#pragma unroll
                            for (int p = 0; p < 8; p++) {
                                float d = fmaf(w, -1.0f, xr[p + kw]);
                                acc1[p] = fmaf(fabsf(d), -1.0f, acc1[p]);
                            }
                        }
                    }
#pragma unroll
                    for (int k = 0; k < 5; k++) wprev[k] = wcur[k];
                }
            }

            // quad combine over c-quarters (q bits are lane bits 2,3)
#pragma unroll
            for (int p = 0; p < 8; p++) {
                acc0[p] += __shfl_xor_sync(0xffffffffu, acc0[p], 4);
                acc0[p] += __shfl_xor_sync(0xffffffffu, acc0[p], 8);
                acc1[p] += __shfl_xor_sync(0xffffffffu, acc1[p], 4);
                acc1[p] += __shfl_xor_sync(0xffffffffu, acc1[p], 8);
            }

            if (q == 0) {
                // BN partials on raw values
                float lsum = 0.f, lsq = 0.f;
#pragma unroll
                for (int p = 0; p < 8; p++) {
                    lsum += acc0[p]; lsq += acc0[p] * acc0[p];
                }
#pragma unroll
                for (int p = 0; p < 8; p++) {
                    lsum += acc1[p]; lsq += acc1[p] * acc1[p];
                }
                sm.ab.u.b.red_s[oc * 4 + phpair] = lsum;
                sm.ab.u.b.red_q[oc * 4 + phpair] = lsq;

                // 2x2 window max/min (both rows live in this thread)
                float wmx[4], wmn[4];
#pragma unroll
                for (int j = 0; j < 4; j++) {
                    float m0x = fmaxf(acc0[2*j], acc0[2*j+1]);
                    float m1x = fmaxf(acc1[2*j], acc1[2*j+1]);
                    float m0n = fminf(acc0[2*j], acc0[2*j+1]);
                    float m1n = fminf(acc1[2*j], acc1[2*j+1]);
                    wmx[j] = fmaxf(m0x, m1x);
                    wmn[j] = fminf(m0n, m1n);
                }
                float4* op = (float4*)(g_s2mm + ((b * 50 + oc) * 4 + phpair) * 8);
                op[0] = make_float4(wmx[0], wmx[1], wmx[2], wmx[3]);
                op[1] = make_float4(wmn[0], wmn[1], wmn[2], wmn[3]);
            }
        }
        __syncthreads();

        if (tid < 50) {   // per-oc reduce over 4 ph-pairs (deterministic)
            float s = 0.f, q = 0.f;
            for (int t = 0; t < 4; t++) { s += sm.ab.u.b.red_s[tid * 4 + t]; q += sm.ab.u.b.red_q[tid * 4 + t]; }
            g_bsum2[tid * 128 + b] = s;
            g_bsq2[tid * 128 + b]  = q;
        }
    }

    grid_barrier();

    // ======================= STAGE C: bn2+pool + fc1 + partial fc2 =========
    // grid = 16 batch-groups (8 batches) x 8 output slices
    {
        const int bg = blk >> 3;             // 0..15
        const int oq = blk & 7;              // 0..7
        const int b0 = bg * 8;
        const int off   = (oq < 4) ? oq * 63 : 252 + (oq - 4) * 62;
        const int width = (oq < 4) ? 63 : 62;

        // bnparam2: 32 warps cover 50 channels (redundant per block)
        for (int c = wid; c < 50; c += 32) {
            float s = 0.f, q = 0.f;
#pragma unroll
            for (int i = 0; i < 4; i++) {
                const int bb = lane + 32 * i;
                s += g_bsum2[c * 128 + bb];
                q += g_bsq2[c * 128 + bb];
            }
#pragma unroll
            for (int d = 16; d; d >>= 1) {
                s += __shfl_xor_sync(0xffffffffu, s, d);
                q += __shfl_xor_sync(0xffffffffu, q, d);
            }
            if (lane == 0) {
                const float invN = 1.f / (128.f * 8.f * 8.f);
                float m = s * invN;
                float v = q * invN - m * m;
                float sc = gamma2[c] * rsqrtf(v + 1e-5f);
                sm.c.s2s[c] = sc;
                sm.c.s2b[c] = beta2[c] - m * sc;
            }
        }
        __syncthreads();

        // bn2 + pool from window max/min: 8 batches x 800
        for (int i = tid; i < 6400; i += 1024) {
            const int bb = i / 800;
            const int o  = i % 800;
            const int c   = o / 16;
            const int r   = (o % 16) / 4;
            const int col = o % 4;
            const float* wp = g_s2mm + (((b0 + bb) * 50 + c) * 4 + r) * 8;
            const float s = sm.c.s2s[c], be = sm.c.s2b[c];
            sm.c.p_s[bb][o] = fmaxf(fmaf(s, wp[col], be), fmaf(s, wp[4 + col], be));
        }
        __syncthreads();

        // warp handles 2 outputs x 8 batches; x streamed per batch
        const int i0 = wid * 2;
        const bool v0 = (i0 < width), v1 = (i0 + 1 < width);
        const int o0 = off + (v0 ? i0 : 0);
        const int o1 = off + (v1 ? i0 + 1 : 0);
        const float4* wr0 = (const float4*)(fc1_w + o0 * 800);
        const float4* wr1 = (const float4*)(fc1_w + o1 * 800);

        float acc[2][8];
#pragma unroll
        for (int j = 0; j < 2; j++)
#pragma unroll
            for (int bb = 0; bb < 8; bb++) acc[j][bb] = 0.f;

#pragma unroll
        for (int i = 0; i < 7; i++) {
            const int fidx = lane + 32 * i;
            if (fidx < 200) {
                float4 wv0 = wr0[fidx];
                float4 wv1 = wr1[fidx];
#pragma unroll
                for (int bb = 0; bb < 8; bb++) {
                    float4 xv = ((const float4*)sm.c.p_s[bb])[fidx];
                    acc[0][bb] = fmaf(wv0.x, xv.x, acc[0][bb]);
                    acc[0][bb] = fmaf(wv0.y, xv.y, acc[0][bb]);
                    acc[0][bb] = fmaf(wv0.z, xv.z, acc[0][bb]);
                    acc[0][bb] = fmaf(wv0.w, xv.w, acc[0][bb]);
                    acc[1][bb] = fmaf(wv1.x, xv.x, acc[1][bb]);
                    acc[1][bb] = fmaf(wv1.y, xv.y, acc[1][bb]);
                    acc[1][bb] = fmaf(wv1.z, xv.z, acc[1][bb]);
                    acc[1][bb] = fmaf(wv1.w, xv.w, acc[1][bb]);
                }
            }
        }

#pragma unroll
        for (int j = 0; j < 2; j++) {
#pragma unroll
            for (int bb = 0; bb < 8; bb++) {
                float a = acc[j][bb];
#pragma unroll
                for (int d = 16; d; d >>= 1) a += __shfl_xor_sync(0xffffffffu, a, d);
                acc[j][bb] = a;
            }
        }
        // relu(h) -> smem staging for partial fc2
        if (lane == 0) {
            if (v0) {
                const float bia = fc1_b[o0];
#pragma unroll
                for (int bb = 0; bb < 8; bb++)
                    sm.c.hs[i0][bb] = fmaxf(acc[0][bb] + bia, 0.f);
            }
            if (v1) {
                const float bia = fc1_b[o1];
#pragma unroll
                for (int bb = 0; bb < 8; bb++)
                    sm.c.hs[i0 + 1][bb] = fmaxf(acc[1][bb] + bia, 0.f);
            }
        }
        __syncthreads();

        // partial fc2 logits over this slice (deterministic ascending w)
        if (tid < 80) {
            const int bb = tid / 10;
            const int j  = tid % 10;
            const float* w2r = fc2_w + j * 500 + off;
            float p = 0.f;
            for (int w = 0; w < width; w++) p = fmaf(w2r[w], sm.c.hs[w][bb], p);
            g_plog[((b0 + bb) * 8 + oq) * 10 + j] = p;
        }
    }

    grid_barrier();

    // ======================= STAGE D: combine logits + softmax ==============
    {
        const int b = blk;
        if (tid < 10) {
            float a = fc2_b[tid];
            const float* pl = g_plog + b * 80 + tid;
#pragma unroll
            for (int oq = 0; oq < 8; oq++) a += pl[oq * 10];
            sm.d.logits[tid] = a;
        }
        __syncthreads();

        if (tid < 10) {
            const int j = tid;
            float mx = -1e30f;
            for (int t = 0; t < 10; t++) mx = fmaxf(mx, sm.d.logits[t]);
            float sum = 0.f;
            for (int t = 0; t < 10; t++) sum += expf(sm.d.logits[t] - mx);
            out[b * 10 + j] = expf(sm.d.logits[j] - mx) / sum;
        }
    }
}

// ---------------- launch ----------------------------------------------------
extern "C" void kernel_launch(void* const* d_in, const int* in_sizes, int n_in,
                              void* d_out, int out_size) {
    const float* x      = (const float*)d_in[0];
    const float* w1     = (const float*)d_in[1];
    const float* gamma1 = (const float*)d_in[2];
    const float* beta1  = (const float*)d_in[3];
    const float* w2     = (const float*)d_in[4];
    const float* gamma2 = (const float*)d_in[5];
    const float* beta2  = (const float*)d_in[6];
    const float* fc1_w  = (const float*)d_in[7];
    const float* fc1_b  = (const float*)d_in[8];
    const float* fc2_w  = (const float*)d_in[9];
    const float* fc2_b  = (const float*)d_in[10];
    float* out = (float*)d_out;

    mega_k<<<128, 1024>>>(x, w1, gamma1, beta1, w2, gamma2, beta2,
                          fc1_w, fc1_b, fc2_w, fc2_b, out);
}

// round 17
// speedup vs baseline: 1.0571x; 1.0571x over previous
#include <cuda_runtime.h>
#include <math.h>

typedef unsigned long long u64;

// ---------------- scratch (device globals; no allocation allowed) ----------
__device__ float g_h[128 * 500];             // fc1 activations
__device__ __align__(16) float g_w2k[50 * 20 * 5 * 8];  // w2 [oc][c][kh][8] (pad 5->8)
__device__ __align__(16) float g_s2mm[128 * 50 * 4 * 8]; // s2 window [b][oc][prow][max4|min4]

__device__ float g_bsum1[20 * 128], g_bsq1[20 * 128];
__device__ float g_bsum2[50 * 128], g_bsq2[50 * 128];

__device__ u64 g_barctr = 0;  // monotonic epoch barrier counter

// grid-wide barrier: monotonic counter, safe across graph replays
__device__ __forceinline__ void grid_barrier() {
    __syncthreads();
    if (threadIdx.x == 0) {
        __threadfence();
        u64 old = atomicAdd(&g_barctr, 1ULL);
        u64 target = (old / gridDim.x + 1ULL) * (u64)gridDim.x;
        while (*((volatile u64*)&g_barctr) < target) { }
        __threadfence();
    }
    __syncthreads();
}

#define CSTR 148   // padded channel stride (words): 5*CSTR % 32 == 4 -> conflict-free

// ---------------- shared memory layout ---------------------------------------
struct AB {
    float pmax[20 * CSTR];   // pooled-window max of conv1 [c][prow*12+pcol]
    float pmin[20 * CSTR];   // pooled-window min
    union {
        struct { float xs[784]; float ws[500]; float red_s[960]; float red_q[960]; } a;
        struct { float s1s[20]; float s1b[20]; float red_s[200]; float red_q[200]; } b;
    } u;
};
struct SC { float p_s[8][800]; float s2s[50]; float s2b[50]; };
struct SD { float logits[10]; };
union SU { AB ab; SC c; SD d; };

// ---------------- mega kernel ----------------------------------------------
__global__ __launch_bounds__(1024, 1) void mega_k(
    const float* __restrict__ x,      const float* __restrict__ w1,
    const float* __restrict__ gamma1, const float* __restrict__ beta1,
    const float* __restrict__ w2,
    const float* __restrict__ gamma2, const float* __restrict__ beta2,
    const float* __restrict__ fc1_w,  const float* __restrict__ fc1_b,
    const float* __restrict__ fc2_w,  const float* __restrict__ fc2_b,
    float* __restrict__ out)
{
    __shared__ __align__(16) SU sm;

    const int blk  = blockIdx.x;        // 0..127
    const int tid  = threadIdx.x;
    const int wid  = tid / 32;
    const int lane = tid % 32;

    // ======================= STAGE A: adder1 (+ w2 repack) =================
    {
        const int b = blk;
        // w2 repack slice -> kh-major padded layout: 128 blocks x 196 >= 25000
        {
            const int i = b * 196 + tid;
            if (tid < 196 && i < 25000) {
                const int oc = i / 500;
                const int r  = i % 500;
                const int c  = r / 25;
                const int k  = r % 25;
                g_w2k[(((oc * 20 + c) * 5 + (k / 5)) * 8) + (k % 5)] = w2[i];
            }
        }
        for (int i = tid; i < 784; i += 1024) sm.ab.u.a.xs[i] = x[b * 784 + i];
        for (int i = tid; i < 500; i += 1024) sm.ab.u.a.ws[i] = w1[i];
        __syncthreads();

        if (tid < 960) {
            const int oc   = tid / 48;
            const int r    = tid % 48;
            const int half = r / 24;          // pw block: half*12 .. half*12+11
            const int ph   = r % 24;          // (ph, ph^1) pairs on adjacent lanes

            float acc[12];
#pragma unroll
            for (int p = 0; p < 12; p++) acc[p] = 0.f;

#pragma unroll
            for (int kh = 0; kh < 5; kh++) {
                // hoist this kh's 5 weights once (25 LDS/thread total, not 125)
                float wv[5];
#pragma unroll
                for (int k = 0; k < 5; k++) wv[k] = sm.ab.u.a.ws[oc * 25 + kh * 5 + k];

                const float4* xrow = (const float4*)(sm.ab.u.a.xs + (ph + kh) * 28 + half * 12);
                float xr[16];
                float4 v0 = xrow[0], v1 = xrow[1], v2 = xrow[2], v3 = xrow[3];
                xr[0]=v0.x; xr[1]=v0.y; xr[2]=v0.z; xr[3]=v0.w;
                xr[4]=v1.x; xr[5]=v1.y; xr[6]=v1.z; xr[7]=v1.w;
                xr[8]=v2.x; xr[9]=v2.y; xr[10]=v2.z; xr[11]=v2.w;
                xr[12]=v3.x; xr[13]=v3.y; xr[14]=v3.z; xr[15]=v3.w;
#pragma unroll
                for (int kw = 0; kw < 5; kw++) {
                    const float w = wv[kw];
#pragma unroll
                    for (int p = 0; p < 12; p++) {
                        float d = fmaf(w, -1.0f, xr[p + kw]);          // FFMA-imm rt1
                        acc[p]  = fmaf(fabsf(d), -1.0f, acc[p]);       // FFMA-imm rt1
                    }
                }
            }

            // BN partials on raw values
            float lsum = 0.f, lsq = 0.f;
#pragma unroll
            for (int p = 0; p < 12; p++) { lsum += acc[p]; lsq += acc[p] * acc[p]; }
            sm.ab.u.a.red_s[tid] = lsum;
            sm.ab.u.a.red_q[tid] = lsq;

            // column-pair max/min, then row-pair via shuffle with lane+1
            float cmx[6], cmn[6];
#pragma unroll
            for (int j = 0; j < 6; j++) {
                cmx[j] = fmaxf(acc[2*j], acc[2*j+1]);
                cmn[j] = fminf(acc[2*j], acc[2*j+1]);
            }
#pragma unroll
            for (int j = 0; j < 6; j++) {
                float omx = __shfl_down_sync(0xffffffffu, cmx[j], 1);
                float omn = __shfl_down_sync(0xffffffffu, cmn[j], 1);
                cmx[j] = fmaxf(cmx[j], omx);
                cmn[j] = fminf(cmn[j], omn);
            }
            if ((ph & 1) == 0) {
                const int prow = ph >> 1;
                const int base = oc * CSTR + prow * 12 + half * 6;
#pragma unroll
                for (int j = 0; j < 6; j++) {
                    sm.ab.pmax[base + j] = cmx[j];
                    sm.ab.pmin[base + j] = cmn[j];
                }
            }
        }
        __syncthreads();

        if (tid < 960 && (tid % 48) == 0) {   // 20 threads, deterministic
            const int oc = tid / 48;
            float s = 0.f, q = 0.f;
            for (int t = 0; t < 48; t++) { s += sm.ab.u.a.red_s[oc * 48 + t]; q += sm.ab.u.a.red_q[oc * 48 + t]; }
            g_bsum1[oc * 128 + b] = s;
            g_bsq1[oc * 128 + b]  = q;
        }
    }

    grid_barrier();

    // ======================= STAGE B: bn1+pool (in smem) + adder2 ==========
    // thread = (oc 0..49, sub = cquarter*4 + phpair): 2 output rows, 5 channels
    {
        const int b = blk;

        // bnparam1: warp per channel (redundant per block, deterministic)
        if (wid < 20) {
            float s = 0.f, q = 0.f;
#pragma unroll
            for (int i = 0; i < 4; i++) {
                const int bb = lane + 32 * i;
                s += g_bsum1[wid * 128 + bb];
                q += g_bsq1[wid * 128 + bb];
            }
#pragma unroll
            for (int d = 16; d; d >>= 1) {
                s += __shfl_xor_sync(0xffffffffu, s, d);
                q += __shfl_xor_sync(0xffffffffu, q, d);
            }
            if (lane == 0) {
                const float invN = 1.f / (128.f * 24.f * 24.f);
                float m = s * invN;
                float v = q * invN - m * m;
                float sc = gamma1[wid] * rsqrtf(v + 1e-5f);
                sm.ab.u.b.s1s[wid] = sc;
                sm.ab.u.b.s1b[wid] = beta1[wid] - m * sc;
            }
        }
        __syncthreads();

        // bn1 + pool, in place over pmax: pool = max(s*mx+be, s*mn+be)
        for (int i = tid; i < 20 * CSTR; i += 1024) {
            const int c   = i / CSTR;
            const int rem = i % CSTR;
            if (rem < 144) {
                const float s = sm.ab.u.b.s1s[c], be = sm.ab.u.b.s1b[c];
                float v = fmaxf(fmaf(s, sm.ab.pmax[i], be), fmaf(s, sm.ab.pmin[i], be));
                sm.ab.pmax[i] = v;
            }
        }
        __syncthreads();

        if (tid < 800) {
            const int oc     = tid / 16;
            const int sub    = tid % 16;
            const int q      = sub >> 2;        // c quarter: q*5 .. q*5+4
            const int phpair = sub & 3;         // rows ph0, ph0+1
            const int ph0    = phpair * 2;

            float acc0[8], acc1[8];
#pragma unroll
            for (int p = 0; p < 8; p++) { acc0[p] = 0.f; acc1[p] = 0.f; }

#pragma unroll
            for (int cc = 0; cc < 5; cc++) {
                const int c = q * 5 + cc;
                const float* xc = sm.ab.pmax + c * CSTR + ph0 * 12;
                const float4* wk = (const float4*)(g_w2k + ((oc * 20 + c) * 5) * 8);

                float wprev[5];
#pragma unroll
                for (int r = 0; r < 6; r++) {
                    float wcur[5];
                    if (r < 5) {
                        float4 wa = wk[r * 2];
                        float4 wb = wk[r * 2 + 1];
                        wcur[0] = wa.x; wcur[1] = wa.y; wcur[2] = wa.z;
                        wcur[3] = wa.w; wcur[4] = wb.x;
                    }
                    const float4* xrow = (const float4*)(xc + r * 12);
                    float4 v0 = xrow[0], v1 = xrow[1], v2 = xrow[2];
                    float xr[12];
                    xr[0]=v0.x; xr[1]=v0.y; xr[2]=v0.z; xr[3]=v0.w;
                    xr[4]=v1.x; xr[5]=v1.y; xr[6]=v1.z; xr[7]=v1.w;
                    xr[8]=v2.x; xr[9]=v2.y; xr[10]=v2.z; xr[11]=v2.w;

                    if (r < 5) {   // row0: kh = r
#pragma unroll
                        for (int kw = 0; kw < 5; kw++) {
                            const float w = wcur[kw];
#pragma unroll
                            for (int p = 0; p < 8; p++) {
                                float d = fmaf(w, -1.0f, xr[p + kw]);
                                acc0[p] = fmaf(fabsf(d), -1.0f, acc0[p]);
                            }
                        }
                    }
                    if (r >= 1) {  // row1: kh = r-1
#pragma unroll
                        for (int kw = 0; kw < 5; kw++) {
                            const float w = wprev[kw];
#pragma unroll
                            for (int p = 0; p < 8; p++) {
                                float d = fmaf(w, -1.0f, xr[p + kw]);
                                acc1[p] = fmaf(fabsf(d), -1.0f, acc1[p]);
                            }
                        }
                    }
#pragma unroll
                    for (int k = 0; k < 5; k++) wprev[k] = wcur[k];
                }
            }

            // quad combine over c-quarters (q bits are lane bits 2,3)
#pragma unroll
            for (int p = 0; p < 8; p++) {
                acc0[p] += __shfl_xor_sync(0xffffffffu, acc0[p], 4);
                acc0[p] += __shfl_xor_sync(0xffffffffu, acc0[p], 8);
                acc1[p] += __shfl_xor_sync(0xffffffffu, acc1[p], 4);
                acc1[p] += __shfl_xor_sync(0xffffffffu, acc1[p], 8);
            }

            if (q == 0) {
                // BN partials on raw values
                float lsum = 0.f, lsq = 0.f;
#pragma unroll
                for (int p = 0; p < 8; p++) {
                    lsum += acc0[p]; lsq += acc0[p] * acc0[p];
                }
#pragma unroll
                for (int p = 0; p < 8; p++) {
                    lsum += acc1[p]; lsq += acc1[p] * acc1[p];
                }
                sm.ab.u.b.red_s[oc * 4 + phpair] = lsum;
                sm.ab.u.b.red_q[oc * 4 + phpair] = lsq;

                // 2x2 window max/min (both rows live in this thread)
                float wmx[4], wmn[4];
#pragma unroll
                for (int j = 0; j < 4; j++) {
                    float m0x = fmaxf(acc0[2*j], acc0[2*j+1]);
                    float m1x = fmaxf(acc1[2*j], acc1[2*j+1]);
                    float m0n = fminf(acc0[2*j], acc0[2*j+1]);
                    float m1n = fminf(acc1[2*j], acc1[2*j+1]);
                    wmx[j] = fmaxf(m0x, m1x);
                    wmn[j] = fminf(m0n, m1n);
                }
                float4* op = (float4*)(g_s2mm + ((b * 50 + oc) * 4 + phpair) * 8);
                op[0] = make_float4(wmx[0], wmx[1], wmx[2], wmx[3]);
                op[1] = make_float4(wmn[0], wmn[1], wmn[2], wmn[3]);
            }
        }
        __syncthreads();

        if (tid < 50) {   // per-oc reduce over 4 ph-pairs (deterministic)
            float s = 0.f, q = 0.f;
            for (int t = 0; t < 4; t++) { s += sm.ab.u.b.red_s[tid * 4 + t]; q += sm.ab.u.b.red_q[tid * 4 + t]; }
            g_bsum2[tid * 128 + b] = s;
            g_bsq2[tid * 128 + b]  = q;
        }
    }

    grid_barrier();

    // ======================= STAGE C: bn2+pool + fc1 ========================
    // grid = 16 batch-groups (8 batches) x 8 output slices
    {
        const int bg = blk >> 3;             // 0..15
        const int oq = blk & 7;              // 0..7
        const int b0 = bg * 8;
        const int off   = (oq < 4) ? oq * 63 : 252 + (oq - 4) * 62;
        const int width = (oq < 4) ? 63 : 62;

        // bnparam2: 32 warps cover 50 channels (redundant per block)
        for (int c = wid; c < 50; c += 32) {
            float s = 0.f, q = 0.f;
#pragma unroll
            for (int i = 0; i < 4; i++) {
                const int bb = lane + 32 * i;
                s += g_bsum2[c * 128 + bb];
                q += g_bsq2[c * 128 + bb];
            }
#pragma unroll
            for (int d = 16; d; d >>= 1) {
                s += __shfl_xor_sync(0xffffffffu, s, d);
                q += __shfl_xor_sync(0xffffffffu, q, d);
            }
            if (lane == 0) {
                const float invN = 1.f / (128.f * 8.f * 8.f);
                float m = s * invN;
                float v = q * invN - m * m;
                float sc = gamma2[c] * rsqrtf(v + 1e-5f);
                sm.c.s2s[c] = sc;
                sm.c.s2b[c] = beta2[c] - m * sc;
            }
        }
        __syncthreads();

        // bn2 + pool from window max/min: 8 batches x 800
        for (int i = tid; i < 6400; i += 1024) {
            const int bb = i / 800;
            const int o  = i % 800;
            const int c   = o / 16;
            const int r   = (o % 16) / 4;
            const int col = o % 4;
            const float* wp = g_s2mm + (((b0 + bb) * 50 + c) * 4 + r) * 8;
            const float s = sm.c.s2s[c], be = sm.c.s2b[c];
            sm.c.p_s[bb][o] = fmaxf(fmaf(s, wp[col], be), fmaf(s, wp[4 + col], be));
        }
        __syncthreads();

        // warp handles 2 outputs x 8 batches; x streamed per batch
        const int i0 = wid * 2;
        const bool v0 = (i0 < width), v1 = (i0 + 1 < width);
        const int o0 = off + (v0 ? i0 : 0);
        const int o1 = off + (v1 ? i0 + 1 : 0);
        const float4* wr0 = (const float4*)(fc1_w + o0 * 800);
        const float4* wr1 = (const float4*)(fc1_w + o1 * 800);

        float acc[2][8];
#pragma unroll
        for (int j = 0; j < 2; j++)
#pragma unroll
            for (int bb = 0; bb < 8; bb++) acc[j][bb] = 0.f;

#pragma unroll
        for (int i = 0; i < 7; i++) {
            const int fidx = lane + 32 * i;
            if (fidx < 200) {
                float4 wv0 = wr0[fidx];
                float4 wv1 = wr1[fidx];
#pragma unroll
                for (int bb = 0; bb < 8; bb++) {
                    float4 xv = ((const float4*)sm.c.p_s[bb])[fidx];
                    acc[0][bb] = fmaf(wv0.x, xv.x, acc[0][bb]);
                    acc[0][bb] = fmaf(wv0.y, xv.y, acc[0][bb]);
                    acc[0][bb] = fmaf(wv0.z, xv.z, acc[0][bb]);
                    acc[0][bb] = fmaf(wv0.w, xv.w, acc[0][bb]);
                    acc[1][bb] = fmaf(wv1.x, xv.x, acc[1][bb]);
                    acc[1][bb] = fmaf(wv1.y, xv.y, acc[1][bb]);
                    acc[1][bb] = fmaf(wv1.z, xv.z, acc[1][bb]);
                    acc[1][bb] = fmaf(wv1.w, xv.w, acc[1][bb]);
                }
            }
        }

#pragma unroll
        for (int j = 0; j < 2; j++) {
#pragma unroll
            for (int bb = 0; bb < 8; bb++) {
                float a = acc[j][bb];
#pragma unroll
                for (int d = 16; d; d >>= 1) a += __shfl_xor_sync(0xffffffffu, a, d);
                acc[j][bb] = a;
            }
        }
        if (lane == 0) {
            if (v0) {
                const float bia = fc1_b[o0];
#pragma unroll
                for (int bb = 0; bb < 8; bb++)
                    g_h[(b0 + bb) * 500 + o0] = fmaxf(acc[0][bb] + bia, 0.f);
            }
            if (v1) {
                const float bia = fc1_b[o1];
#pragma unroll
                for (int bb = 0; bb < 8; bb++)
                    g_h[(b0 + bb) * 500 + o1] = fmaxf(acc[1][bb] + bia, 0.f);
            }
        }
    }

    grid_barrier();

    // ======================= STAGE D: fc2 + softmax =========================
    {
        const int b = blk;
        if (tid < 320) {
            float a = 0.f;
            const float* wr = fc2_w + wid * 500;
            const float* hr = g_h + b * 500;
#pragma unroll
            for (int i = 0; i < 16; i++) {
                int k = lane + 32 * i;
                if (k < 500) a = fmaf(wr[k], hr[k], a);
            }
#pragma unroll
            for (int d = 16; d; d >>= 1) a += __shfl_xor_sync(0xffffffffu, a, d);
            if (lane == 0) sm.d.logits[wid] = a + fc2_b[wid];
        }
        __syncthreads();

        if (tid < 10) {
            const int j = tid;
            float mx = -1e30f;
            for (int t = 0; t < 10; t++) mx = fmaxf(mx, sm.d.logits[t]);
            float sum = 0.f;
            for (int t = 0; t < 10; t++) sum += expf(sm.d.logits[t] - mx);
            out[b * 10 + j] = expf(sm.d.logits[j] - mx) / sum;
        }
    }
}

// ---------------- launch ----------------------------------------------------
extern "C" void kernel_launch(void* const* d_in, const int* in_sizes, int n_in,
                              void* d_out, int out_size) {
    const float* x      = (const float*)d_in[0];
    const float* w1     = (const float*)d_in[1];
    const float* gamma1 = (const float*)d_in[2];
    const float* beta1  = (const float*)d_in[3];
    const float* w2     = (const float*)d_in[4];
    const float* gamma2 = (const float*)d_in[5];
    const float* beta2  = (const float*)d_in[6];
    const float* fc1_w  = (const float*)d_in[7];
    const float* fc1_b  = (const float*)d_in[8];
    const float* fc2_w  = (const float*)d_in[9];
    const float* fc2_b  = (const float*)d_in[10];
    float* out = (float*)d_out;

    mega_k<<<128, 1024>>>(x, w1, gamma1, beta1, w2, gamma2, beta2,
                          fc1_w, fc1_b, fc2_w, fc2_b, out);
}